// round 13
// baseline (speedup 1.0000x reference)
#include <cuda_runtime.h>
#include <math.h>
#include <stdint.h>

#define NN    8192
#define KK1   7372
#define KK2   5160
#define PSTRIDE (8192*128)
typedef unsigned long long u64;

__device__ float g_A2[(size_t)KK1 * KK1];
__device__ float g_A3[(size_t)KK2 * KK2];
__device__ float g_T[8 * (size_t)PSTRIDE];
__device__ float g_xs1[NN*48], g_xs2[NN*48], g_xs3[NN*48];
__device__ float g_xorg[NN*48];
__device__ float g_u1[NN*48], g_u2[NN*48], g_u3[NN*48];
__device__ float g_xd1[NN*48], g_xd2[NN*48];
__device__ float g_h1[NN*48], g_P[NN*48], g_pre[NN*48];
__device__ float g_y1[NN*48], g_y2[NN*48], g_y3[NN*48];
__device__ float g_x12[NN*48], g_x21[NN*48], g_x23[NN*48], g_x32[NN*48];
__device__ float g_Z[NN*48], g_tmp[NN*48], g_tmp2[NN*48];
__device__ float g_cat[NN*96];
__device__ float g_val1[NN], g_val2[NN];
__device__ int   g_idx1[NN], g_idx2[NN];
__device__ unsigned long long g_keys[NN];

__device__ __forceinline__ u64 pack2(float lo, float hi) {
    u64 r; asm("mov.b64 %0, {%1,%2};" : "=l"(r) : "f"(lo), "f"(hi)); return r;
}
__device__ __forceinline__ void unpack2(u64 v, float& lo, float& hi) {
    asm("mov.b64 {%0,%1}, %2;" : "=f"(lo), "=f"(hi) : "l"(v));
}
__device__ __forceinline__ u64 ffma2(u64 a, u64 b, u64 c) {
    u64 d; asm("fma.rn.f32x2 %0, %1, %2, %3;" : "=l"(d) : "l"(a), "l"(b), "l"(c)); return d;
}
__device__ __forceinline__ u64 add2(u64 a, u64 b) {
    u64 d; asm("add.rn.f32x2 %0, %1, %2;" : "=l"(d) : "l"(a), "l"(b)); return d;
}

// ---- main GEMM: Cpart[kz] = A[MxK](lda) @ B[KxNC]; TM rows/thread ----
template<int NC, int TN, int TM>
__global__ __launch_bounds__(256)
void gemm3_kernel(const float* __restrict__ A, int lda, const float* __restrict__ B,
                  float* __restrict__ Cpart, int M, int K, int nsplit)
{
    constexpr int NGRP = NC / TN;
    constexpr int RP   = 256 / NGRP;
    constexpr int BM   = TM * RP;
    constexpr int TNP  = TN / 2;
    constexpr int TNQ  = TN / 4;
    __shared__ float As[BM][33];
    __shared__ float Bs[32][NC];

    const int tid  = threadIdx.x;
    const int row0 = blockIdx.x * BM;
    const int kz   = blockIdx.y;
    const int nch  = (K + 31) >> 5;
    const int c0   = (int)(((long long)nch * kz) / nsplit);
    const int c1   = (int)(((long long)nch * (kz + 1)) / nsplit);
    const int rowg = tid & (RP - 1);
    const int colg = tid / RP;

    const u64 neg1 = pack2(-1.f, -1.f);
    u64 acc[TM][TNP], cmp[TM][TNP];
    #pragma unroll
    for (int t = 0; t < TM; t++)
        #pragma unroll
        for (int p = 0; p < TNP; p++) { acc[t][p] = 0ull; cmp[t][p] = 0ull; }

    for (int ch = c0; ch < c1; ++ch) {
        const int kb = ch << 5;
        #pragma unroll
        for (int i = 0; i < (BM * 32) / 1024; i++) {
            int l = tid + (i << 8);
            int r = l >> 3, c4 = (l & 7) << 2;
            int grow = row0 + r;
            float4 v = make_float4(0.f, 0.f, 0.f, 0.f);
            if (grow < M) {
                int gc = kb + c4;
                const float* src = A + (size_t)grow * lda + gc;
                if (gc + 3 < K) v = *reinterpret_cast<const float4*>(src);
                else {
                    if (gc     < K) v.x = src[0];
                    if (gc + 1 < K) v.y = src[1];
                    if (gc + 2 < K) v.z = src[2];
                }
            }
            As[r][c4 + 0] = v.x; As[r][c4 + 1] = v.y;
            As[r][c4 + 2] = v.z; As[r][c4 + 3] = v.w;
        }
        #pragma unroll
        for (int i = 0; i < (32 * NC) / 256; i++) {
            int l = tid + (i << 8);
            int r = l / NC, c = l - r * NC;
            int gk = kb + r;
            Bs[r][c] = (gk < K) ? B[(size_t)gk * NC + c] : 0.f;
        }
        __syncthreads();

        u64 part[TM][TNP];
        #pragma unroll
        for (int t = 0; t < TM; t++)
            #pragma unroll
            for (int p = 0; p < TNP; p++) part[t][p] = 0ull;

        #pragma unroll
        for (int kk = 0; kk < 32; ++kk) {
            u64 av[TM];
            #pragma unroll
            for (int t = 0; t < TM; t++) {
                float a = As[rowg + t * RP][kk];
                av[t] = pack2(a, a);
            }
            u64 bq[TNP];
            #pragma unroll
            for (int q = 0; q < TNQ; q++) {
                ulonglong2 bb = *reinterpret_cast<const ulonglong2*>(&Bs[kk][colg * TN + 4 * q]);
                bq[2 * q] = bb.x; bq[2 * q + 1] = bb.y;
            }
            #pragma unroll
            for (int t = 0; t < TM; t++)
                #pragma unroll
                for (int p = 0; p < TNP; p++)
                    part[t][p] = ffma2(av[t], bq[p], part[t][p]);
        }
        #pragma unroll
        for (int t = 0; t < TM; t++)
            #pragma unroll
            for (int p = 0; p < TNP; p++) {
                u64 y = ffma2(cmp[t][p], neg1, part[t][p]);
                u64 s = add2(acc[t][p], y);
                u64 d = ffma2(acc[t][p], neg1, s);
                cmp[t][p] = ffma2(y, neg1, d);
                acc[t][p] = s;
            }
        __syncthreads();
    }

    float* Cb = Cpart + (size_t)kz * PSTRIDE;
    #pragma unroll
    for (int t = 0; t < TM; t++) {
        int grow = row0 + rowg + t * RP;
        if (grow < M) {
            #pragma unroll
            for (int p = 0; p < TNP; p++) {
                float lo, hi; unpack2(acc[t][p], lo, hi);
                Cb[(size_t)grow * NC + colg * TN + 2 * p]     = lo;
                Cb[(size_t)grow * NC + colg * TN + 2 * p + 1] = hi;
            }
        }
    }
}

// Y[m, 0..48) = act( sum_splits T[m, col0..col0+48) + b + add )
__global__ void ss_kernel(const float* __restrict__ T, int srcNC, int col0, int nsplit,
                          const float* __restrict__ b, int act,
                          const float* __restrict__ add, float* __restrict__ Y, int M)
{
    int e = blockIdx.x * blockDim.x + threadIdx.x;
    if (e >= M * 12) return;
    int m = e / 12, j4 = e - m * 12;
    size_t off = (size_t)m * srcNC + col0 + j4 * 4;
    float4 s = *reinterpret_cast<const float4*>(T + off);
    for (int sp = 1; sp < nsplit; sp++) {
        float4 v = *reinterpret_cast<const float4*>(T + (size_t)sp * PSTRIDE + off);
        s.x += v.x; s.y += v.y; s.z += v.z; s.w += v.w;
    }
    if (b) {
        float4 bb = *reinterpret_cast<const float4*>(b + j4 * 4);
        s.x += bb.x; s.y += bb.y; s.z += bb.z; s.w += bb.w;
    }
    if (add) {
        float4 av = *reinterpret_cast<const float4*>(add + (size_t)m * 48 + j4 * 4);
        s.x += av.x; s.y += av.y; s.z += av.z; s.w += av.w;
    }
    if (act == 1) {
        s.x = fmaxf(s.x, 0.f); s.y = fmaxf(s.y, 0.f);
        s.z = fmaxf(s.z, 0.f); s.w = fmaxf(s.w, 0.f);
    }
    *reinterpret_cast<float4*>(Y + (size_t)m * 48 + j4 * 4) = s;
}

// small GEMM: out[m, ocol..ocol+48) = act( f(X[m,:ncin]) @ W[48,ncin]^T + b + b2 )
__global__ __launch_bounds__(256)
void sgemm_kernel(const float* __restrict__ X, int M, int ncin,
                  const float* __restrict__ W, const float* __restrict__ b,
                  const float* __restrict__ b2, const float* __restrict__ alpha_p,
                  int act, int insig, float* __restrict__ out, int ostride, int ocol)
{
    __shared__ float Xs[32][129];
    __shared__ float Wt[128][50];
    const int tid = threadIdx.x;
    const int row0 = blockIdx.x * 32;
    for (int idx = tid; idx < 48 * ncin; idx += 256) {
        int j = idx / ncin, i = idx - j * ncin;
        Wt[i][j] = W[idx];
    }
    for (int idx = tid; idx < 32 * ncin; idx += 256) {
        int r = idx / ncin, c = idx - r * ncin;
        int g = row0 + r;
        float v = (g < M) ? X[(size_t)g * ncin + c] : 0.f;
        if (insig) v = 1.f / (1.f + expf(-v));
        Xs[r][c] = v;
    }
    __syncthreads();
    const int m = tid & 31, jg = tid >> 5;
    u64 acc[3] = {0ull, 0ull, 0ull};
    #pragma unroll 8
    for (int i = 0; i < ncin; i++) {
        float a = Xs[m][i];
        u64 av = pack2(a, a);
        const u64* wp = reinterpret_cast<const u64*>(&Wt[i][jg * 6]);
        acc[0] = ffma2(av, wp[0], acc[0]);
        acc[1] = ffma2(av, wp[1], acc[1]);
        acc[2] = ffma2(av, wp[2], acc[2]);
    }
    int g = row0 + m;
    if (g < M) {
        float al = alpha_p ? *alpha_p : 0.f;
        #pragma unroll
        for (int p = 0; p < 3; p++) {
            float lo, hi; unpack2(acc[p], lo, hi);
            int j = jg * 6 + 2 * p;
            if (b)  { lo += b[j];  hi += b[j + 1]; }
            if (b2) { lo += b2[j]; hi += b2[j + 1]; }
            if (act == 2) { if (lo < 0.f) lo *= al; if (hi < 0.f) hi *= al; }
            out[(size_t)g * ostride + ocol + j]     = lo;
            out[(size_t)g * ostride + ocol + j + 1] = hi;
        }
    }
}

__global__ void sc_kernel(const float* __restrict__ h1, const float* __restrict__ P,
                          const int* __restrict__ perm, const float* __restrict__ db_p,
                          float* __restrict__ ret, unsigned long long* __restrict__ keys, int M)
{
    int n = blockIdx.x * blockDim.x + threadIdx.x;
    if (n >= NN) return;
    if (n < M) {
        float db = *db_p;
        const float* pr = P + (size_t)n * 48;
        const float* h  = h1 + (size_t)n * 48;
        const float* h2 = h1 + (size_t)perm[n] * 48;
        double s1 = 0.0, s2 = 0.0;
        #pragma unroll 8
        for (int i = 0; i < 48; i++) {
            s1 = fma((double)h[i],  (double)pr[i], s1);
            s2 = fma((double)h2[i], (double)pr[i], s2);
        }
        float s1f = (float)s1 + db, s2f = (float)s2 + db;
        ret[n] = s1f; ret[M + n] = s2f;
        float score = 1.f / (1.f + expf(-s1f));
        keys[n] = ((unsigned long long)(~__float_as_uint(score)) << 32) | (unsigned)n;
    } else {
        keys[n] = (0xFFFFFFFFull << 32) | (unsigned)n;
    }
}

__global__ void sort_kernel(const unsigned long long* __restrict__ keys,
                            int* __restrict__ idx_out, float* __restrict__ val_out, int topk)
{
    extern __shared__ unsigned long long s[];
    const int n = NN;
    for (int i = threadIdx.x; i < n; i += blockDim.x) s[i] = keys[i];
    __syncthreads();
    for (int k = 2; k <= n; k <<= 1)
        for (int j = k >> 1; j > 0; j >>= 1) {
            for (int t = threadIdx.x; t < n; t += blockDim.x) {
                int ixj = t ^ j;
                if (ixj > t) {
                    bool up = ((t & k) == 0);
                    unsigned long long xv = s[t], yv = s[ixj];
                    if ((xv > yv) == up) { s[t] = yv; s[ixj] = xv; }
                }
            }
            __syncthreads();
        }
    for (int r = threadIdx.x; r < topk; r += blockDim.x) {
        unsigned long long kv = s[r];
        idx_out[r] = (int)(kv & 0xffffffffu);
        val_out[r] = __uint_as_float(~(unsigned int)(kv >> 32));
    }
}

__global__ void poolgather_kernel(const float* __restrict__ X, const int* __restrict__ idx,
                                  const float* __restrict__ val, float* __restrict__ Y, int Kn)
{
    int e = blockIdx.x * blockDim.x + threadIdx.x;
    if (e >= Kn * 48) return;
    int r = e / 48, c = e - r * 48;
    Y[e] = X[(size_t)idx[r] * 48 + c] * val[r];
}

__global__ void scatter2_kernel(const float* __restrict__ X, const int* __restrict__ idx,
                                int Kn, float* __restrict__ Z, int zstride, int col0)
{
    int e = blockIdx.x * blockDim.x + threadIdx.x;
    if (e >= Kn * 48) return;
    int r = e / 48, c = e - r * 48;
    Z[(size_t)idx[r] * zstride + col0 + c] = X[e];
}

__global__ void combine_kernel(const float* __restrict__ a, const float* __restrict__ b, float sb,
                               const float* __restrict__ c, float sc,
                               const float* __restrict__ d, float* __restrict__ o, int n)
{
    int i = blockIdx.x * blockDim.x + threadIdx.x;
    if (i >= n) return;
    float v = fmaf(sb, b[i], a[i]);
    if (c) v = fmaf(sc, c[i], v);
    if (d) v += d[i];
    o[i] = v;
}

__global__ void cat_kernel(const float* __restrict__ xa, const float* __restrict__ xo,
                           float* __restrict__ cat, int M)
{
    int e = blockIdx.x * blockDim.x + threadIdx.x;
    if (e >= M * 96) return;
    int m = e / 96, c = e - m * 96;
    cat[e] = (c < 48) ? xa[(size_t)m * 48 + c] : xo[(size_t)m * 48 + (c - 48)];
}

__global__ void gatherA_kernel(const float* __restrict__ A, int lda,
                               const int* __restrict__ idx, int Ksz, float* __restrict__ out)
{
    const float* arow = A + (size_t)__ldg(&idx[blockIdx.x]) * lda;
    float* orow = out + (size_t)blockIdx.x * Ksz;
    for (int j = threadIdx.x; j < Ksz; j += blockDim.x)
        orow[j] = arow[__ldg(&idx[j])];
}

static void* symaddr(const void* sym) { void* p = nullptr; cudaGetSymbolAddress(&p, sym); return p; }

extern "C" void kernel_launch(void* const* d_in, const int* in_sizes, int n_in,
                              void* d_out, int out_size)
{
    const float* A      = (const float*)d_in[0];
    const float* x      = (const float*)d_in[1];
    const int*   perm1  = (const int*)  d_in[2];
    const int*   perm2  = (const int*)  d_in[3];
    const float* W_in   = (const float*)d_in[4];
    const float* b_in   = (const float*)d_in[5];
    const float* W_dd   = (const float*)d_in[6];
    const float* b_dd   = (const float*)d_in[7];
    const float* W_end  = (const float*)d_in[8];
    const float* b_end  = (const float*)d_in[9];
    const float* mlp_b2 = (const float*)d_in[10];
    const float* prelu_a= (const float*)d_in[11];
    const float* disc_W = (const float*)d_in[12];
    const float* disc_b = (const float*)d_in[13];

    float* out  = (float*)d_out;
    float* ret1 = out + (size_t)NN * 48;
    float* ret2 = ret1 + 2 * NN;

    float* A2  = (float*)symaddr(g_A2);   float* A3  = (float*)symaddr(g_A3);
    float* T   = (float*)symaddr(g_T);
    float* xs1 = (float*)symaddr(g_xs1);  float* xs2 = (float*)symaddr(g_xs2);
    float* xs3 = (float*)symaddr(g_xs3);  float* xorg= (float*)symaddr(g_xorg);
    float* u1  = (float*)symaddr(g_u1);   float* u2  = (float*)symaddr(g_u2);
    float* u3  = (float*)symaddr(g_u3);
    float* xd1 = (float*)symaddr(g_xd1);  float* xd2 = (float*)symaddr(g_xd2);
    float* h1  = (float*)symaddr(g_h1);   float* P   = (float*)symaddr(g_P);
    float* pre = (float*)symaddr(g_pre);
    float* y1  = (float*)symaddr(g_y1);   float* y2  = (float*)symaddr(g_y2);
    float* y3  = (float*)symaddr(g_y3);
    float* x12 = (float*)symaddr(g_x12);  float* x21 = (float*)symaddr(g_x21);
    float* x23 = (float*)symaddr(g_x23);  float* x32 = (float*)symaddr(g_x32);
    float* Z   = (float*)symaddr(g_Z);    float* tmp = (float*)symaddr(g_tmp);
    float* tmp2= (float*)symaddr(g_tmp2); float* B96 = (float*)symaddr(g_cat);
    float* val1= (float*)symaddr(g_val1); float* val2= (float*)symaddr(g_val2);
    int* idx1  = (int*)symaddr(g_idx1);   int* idx2  = (int*)symaddr(g_idx2);
    unsigned long long* keys = (unsigned long long*)symaddr(g_keys);

    cudaFuncSetAttribute(sort_kernel, cudaFuncAttributeMaxDynamicSharedMemorySize, NN * 8);

    const int NSPL = 8;
    #define Wd(i) (W_dd + (size_t)(i) * 2304)
    #define bd(i) (b_dd + (i) * 48)

    auto sg = [&](const float* X, int M, int ncin, const float* W, const float* b,
                  const float* b2, const float* ap, int act, int insig,
                  float* o, int ostride, int ocol) {
        sgemm_kernel<<<(M + 31) / 32, 256>>>(X, M, ncin, W, b, b2, ap, act, insig, o, ostride, ocol);
    };
    auto g48 = [&](const float* Am, int lda, const float* Bm, int M, int K) {
        dim3 g((M + 255) / 256, NSPL);
        gemm3_kernel<48, 12, 4><<<g, 256>>>(Am, lda, Bm, T, M, K, NSPL);
    };
    auto g96 = [&](const float* Am, int lda, const float* Bm, int M, int K) {
        dim3 g((M + 127) / 128, NSPL);
        gemm3_kernel<96, 12, 4><<<g, 256>>>(Am, lda, Bm, T, M, K, NSPL);
    };
    auto ss = [&](int srcNC, int col0, const float* b, int act, const float* add,
                  float* Y, int M) {
        ss_kernel<<<(M * 12 + 255) / 256, 256>>>(T, srcNC, col0, NSPL, b, act, add, Y, M);
    };
    auto pg = [&](const float* X, const int* idx, const float* val, float* Y, int Kn) {
        poolgather_kernel<<<(Kn * 48 + 255) / 256, 256>>>(X, idx, val, Y, Kn);
    };
    auto sct = [&](const float* X, const int* idx, int Kn, float* Zb, int zstride, int col0) {
        scatter2_kernel<<<(Kn * 48 + 255) / 256, 256>>>(X, idx, Kn, Zb, zstride, col0);
    };
    auto comb = [&](const float* a, const float* b, float sb, const float* c, float sc,
                    const float* d, float* o, int n) {
        combine_kernel<<<(n + 255) / 256, 256>>>(a, b, sb, c, sc, d, o, n);
    };
    auto gcn = [&](const float* Am, int lda, int Mk, const float* X, const float* W,
                   const float* b, int act, const float* add, float* Y) {
        sg(X, Mk, 48, W, nullptr, nullptr, nullptr, 0, 0, pre, 48, 0);
        g48(Am, lda, pre, Mk, Mk);
        ss(48, 0, b, act, add, Y, Mk);
    };
    auto cross_pair = [&](const float* Am, int lda, int Mk,
                          const float* Xa, const float* Wa, const float* ba, float* Ya,
                          const float* Xb, int Mb, const float* Wb, const float* bb, float* Yb,
                          const int* idx) {
        cudaMemsetAsync(B96, 0, (size_t)Mk * 96 * sizeof(float));
        sg(Xa, Mk, 48, Wa, nullptr, nullptr, nullptr, 0, 0, B96, 96, 0);
        sg(Xb, Mb, 48, Wb, nullptr, nullptr, nullptr, 0, 0, pre, 48, 0);
        sct(pre, idx, Mb, B96, 96, 48);
        g96(Am, lda, B96, Mk, Mk);
        ss(96, 0,  ba, 0, nullptr, Ya, Mk);
        ss(96, 48, bb, 0, nullptr, Yb, Mk);
    };

    // ---- phase 0: x_s1 = A @ (x @ W_in^T) + b_in ----
    sg(x, NN, 128, W_in, nullptr, nullptr, nullptr, 0, 0, pre, 48, 0);
    g48(A, NN, pre, NN, NN);
    ss(48, 0, b_in, 0, nullptr, xs1, NN);
    cudaMemcpyAsync(xorg, xs1, (size_t)NN * 48 * sizeof(float), cudaMemcpyDeviceToDevice);

    // ---- index_select scale 1 (fc=1, gcn=2, m=0) ----
    sg(xs1, NN, 48, Wd(1), bd(1), mlp_b2, prelu_a, 2, 0, h1, 48, 0);
    gcn(A, NN, NN, h1, Wd(2), bd(2), 0, nullptr, xd1);
    sg(xd1, NN, 48, disc_W, nullptr, nullptr, nullptr, 0, 1, P, 48, 0);
    sc_kernel<<<NN / 256, 256>>>(h1, P, perm1, disc_b + 0, ret1, keys, NN);
    sort_kernel<<<1, 1024, NN * 8>>>(keys, idx1, val1, KK1);
    pg(xs1, idx1, val1, xs2, KK1);
    gatherA_kernel<<<KK1, 256>>>(A, NN, idx1, KK1, A2);
    gcn(A2, KK1, KK1, xs2, Wd(0), bd(0), 0, nullptr, xs2);

    // ---- index_select scale 2 (fc=3, gcn=4, m=1) ----
    sg(xs2, KK1, 48, Wd(3), bd(3), mlp_b2 + 48, prelu_a + 1, 2, 0, h1, 48, 0);
    gcn(A2, KK1, KK1, h1, Wd(4), bd(4), 0, nullptr, xd2);
    sg(xd2, KK1, 48, disc_W + 2304, nullptr, nullptr, nullptr, 0, 1, P, 48, 0);
    sc_kernel<<<NN / 256, 256>>>(h1, P, perm2, disc_b + 1, ret2, keys, KK1);
    sort_kernel<<<1, 1024, NN * 8>>>(keys, idx2, val2, KK2);
    pg(xs2, idx2, val2, xs3, KK2);
    gatherA_kernel<<<KK2, 256>>>(A2, KK1, idx2, KK2, A3);

    // ---- layer 1 ----
    gcn(A,  NN,  NN,  xs1, Wd(5),  bd(5),  1, nullptr, y1);
    gcn(A2, KK1, KK1, xs2, Wd(8),  bd(8),  1, nullptr, y2);
    gcn(A3, KK2, KK2, xs3, Wd(11), bd(11), 1, nullptr, y3);
    cross_pair(A, NN, NN,  y1, Wd(14), bd(14), tmp,  y2, KK1, Wd(15), bd(15), x21, idx1);
    pg(tmp, idx1, val1, x12, KK1);
    cross_pair(A2, KK1, KK1, y2, Wd(16), bd(16), tmp, y3, KK2, Wd(17), bd(17), x32, idx2);
    pg(tmp, idx2, val2, x23, KK2);
    comb(y1, x21, 1.f,  nullptr, 0.f, xs1, u1, NN * 48);
    comb(y2, x12, 0.5f, x32, 0.5f,    xs2, u2, KK1 * 48);
    comb(y3, x23, 1.f,  nullptr, 0.f, xs3, u3, KK2 * 48);

    // ---- layer 2 ----
    gcn(A,  NN,  NN,  u1, Wd(6),  bd(6),  1, nullptr, y1);
    gcn(A2, KK1, KK1, u2, Wd(9),  bd(9),  1, nullptr, y2);
    gcn(A3, KK2, KK2, u3, Wd(12), bd(12), 1, nullptr, y3);
    cross_pair(A, NN, NN,  y1, Wd(18), bd(18), tmp,  y2, KK1, Wd(19), bd(19), x21, idx1);
    pg(tmp, idx1, val1, x12, KK1);
    cross_pair(A2, KK1, KK1, y2, Wd(20), bd(20), tmp, y3, KK2, Wd(21), bd(21), x32, idx2);
    pg(tmp, idx2, val2, x23, KK2);
    comb(y1, x21, 0.05f,  nullptr, 0.f, nullptr, xs1, NN * 48);
    comb(y2, x12, 0.025f, x32, 0.025f,  nullptr, xs2, KK1 * 48);
    comb(y3, x23, 0.05f,  nullptr, 0.f, nullptr, xs3, KK2 * 48);

    // ---- layer 3 ----
    gcn(A,  NN,  NN,  xs1, Wd(7),  bd(7),  1, nullptr, y1);
    gcn(A2, KK1, KK1, xs2, Wd(10), bd(10), 1, nullptr, y2);
    gcn(A3, KK2, KK2, xs3, Wd(13), bd(13), 1, nullptr, y3);

    // ---- fuse ----
    sg(y3, KK2, 48, Wd(23), nullptr, nullptr, nullptr, 0, 0, pre, 48, 0);
    cudaMemsetAsync(Z, 0, (size_t)KK1 * 48 * sizeof(float));
    sct(pre, idx2, KK2, Z, 48, 0);
    g48(A2, KK1, Z, KK1, KK1);
    ss(48, 0, bd(23), 0, xd2, tmp, KK1);
    comb(y2, tmp, 1.f, nullptr, 0.f, nullptr, tmp2, KK1 * 48);
    sg(tmp2, KK1, 48, Wd(22), nullptr, nullptr, nullptr, 0, 0, pre, 48, 0);
    cudaMemsetAsync(Z, 0, (size_t)NN * 48 * sizeof(float));
    sct(pre, idx1, KK1, Z, 48, 0);
    g48(A, NN, Z, NN, NN);
    ss(48, 0, bd(22), 0, nullptr, tmp, NN);
    comb(y1, tmp, 1.f, xd1, 1.f, nullptr, tmp2, NN * 48);
    cat_kernel<<<(NN * 96 + 255) / 256, 256>>>(tmp2, xorg, B96, NN);
    sg(B96, NN, 96, W_end, nullptr, nullptr, nullptr, 0, 0, pre, 48, 0);
    g48(A, NN, pre, NN, NN);
    ss(48, 0, b_end, 0, nullptr, out, NN);
}

// round 14
// speedup vs baseline: 1.6044x; 1.6044x over previous
#include <cuda_runtime.h>
#include <math.h>
#include <stdint.h>

#define NN    8192
#define KK1   7372
#define KK2   5160
#define PSTRIDE (8192*128)
typedef unsigned long long u64;

__device__ float g_A2[(size_t)KK1 * KK1];
__device__ float g_A3[(size_t)KK2 * KK2];
__device__ float g_T[8 * (size_t)PSTRIDE];
__device__ float g_xs1[NN*48], g_xs2[NN*48], g_xs3[NN*48];
__device__ float g_xorg[NN*48];
__device__ float g_u1[NN*48], g_u2[NN*48], g_u3[NN*48];
__device__ float g_xd1[NN*48], g_xd2[NN*48];
__device__ float g_h1[NN*48], g_P[NN*48], g_pre[NN*48];
__device__ float g_y1[NN*48], g_y2[NN*48], g_y3[NN*48];
__device__ float g_x12[NN*48], g_x21[NN*48], g_x23[NN*48], g_x32[NN*48];
__device__ float g_Z[NN*48], g_tmp[NN*48], g_tmp2[NN*48];
__device__ float g_cat[NN*96];
__device__ float g_val1[NN], g_val2[NN];
__device__ int   g_idx1[NN], g_idx2[NN];
__device__ unsigned long long g_keys[NN];

__device__ __forceinline__ u64 pack2(float lo, float hi) {
    u64 r; asm("mov.b64 %0, {%1,%2};" : "=l"(r) : "f"(lo), "f"(hi)); return r;
}
__device__ __forceinline__ void unpack2(u64 v, float& lo, float& hi) {
    asm("mov.b64 {%0,%1}, %2;" : "=f"(lo), "=f"(hi) : "l"(v));
}
__device__ __forceinline__ u64 ffma2(u64 a, u64 b, u64 c) {
    u64 d; asm("fma.rn.f32x2 %0, %1, %2, %3;" : "=l"(d) : "l"(a), "l"(b), "l"(c)); return d;
}
__device__ __forceinline__ u64 add2(u64 a, u64 b) {
    u64 d; asm("add.rn.f32x2 %0, %1, %2;" : "=l"(d) : "l"(a), "l"(b)); return d;
}

// ---- main GEMM: Cpart[kz] = A[MxK](lda) @ B[KxNC]; TM=2 rows/thread ----
template<int NC, int TN>
__global__ __launch_bounds__(256)
void gemm3_kernel(const float* __restrict__ A, int lda, const float* __restrict__ B,
                  float* __restrict__ Cpart, int M, int K, int nsplit)
{
    constexpr int NGRP = NC / TN;
    constexpr int RP   = 256 / NGRP;
    constexpr int BM   = 2 * RP;
    constexpr int TNP  = TN / 2;
    constexpr int TNQ  = TN / 4;
    __shared__ float As[BM][33];
    __shared__ float Bs[32][NC];

    const int tid  = threadIdx.x;
    const int row0 = blockIdx.x * BM;
    const int kz   = blockIdx.y;
    const int nch  = (K + 31) >> 5;
    const int c0   = (int)(((long long)nch * kz) / nsplit);
    const int c1   = (int)(((long long)nch * (kz + 1)) / nsplit);
    const int rowg = tid & (RP - 1);
    const int colg = tid / RP;

    const u64 neg1 = pack2(-1.f, -1.f);
    u64 acc[2][TNP], cmp[2][TNP];
    #pragma unroll
    for (int t = 0; t < 2; t++)
        #pragma unroll
        for (int p = 0; p < TNP; p++) { acc[t][p] = 0ull; cmp[t][p] = 0ull; }

    for (int ch = c0; ch < c1; ++ch) {
        const int kb = ch << 5;
        #pragma unroll
        for (int i = 0; i < (BM * 32) / 1024; i++) {
            int l = tid + (i << 8);
            int r = l >> 3, c4 = (l & 7) << 2;
            int grow = row0 + r;
            float4 v = make_float4(0.f, 0.f, 0.f, 0.f);
            if (grow < M) {
                int gc = kb + c4;
                const float* src = A + (size_t)grow * lda + gc;
                if (gc + 3 < K) v = *reinterpret_cast<const float4*>(src);
                else {
                    if (gc     < K) v.x = src[0];
                    if (gc + 1 < K) v.y = src[1];
                    if (gc + 2 < K) v.z = src[2];
                }
            }
            As[r][c4 + 0] = v.x; As[r][c4 + 1] = v.y;
            As[r][c4 + 2] = v.z; As[r][c4 + 3] = v.w;
        }
        #pragma unroll
        for (int i = 0; i < (32 * NC) / 256; i++) {
            int l = tid + (i << 8);
            int r = l / NC, c = l - r * NC;
            int gk = kb + r;
            Bs[r][c] = (gk < K) ? B[(size_t)gk * NC + c] : 0.f;
        }
        __syncthreads();

        u64 part[2][TNP];
        #pragma unroll
        for (int t = 0; t < 2; t++)
            #pragma unroll
            for (int p = 0; p < TNP; p++) part[t][p] = 0ull;

        #pragma unroll
        for (int kk = 0; kk < 32; ++kk) {
            float a0f = As[rowg][kk];
            float a1f = As[rowg + RP][kk];
            u64 a0 = pack2(a0f, a0f), a1 = pack2(a1f, a1f);
            u64 bq[TNP];
            #pragma unroll
            for (int q = 0; q < TNQ; q++) {
                ulonglong2 bb = *reinterpret_cast<const ulonglong2*>(&Bs[kk][colg * TN + 4 * q]);
                bq[2 * q] = bb.x; bq[2 * q + 1] = bb.y;
            }
            #pragma unroll
            for (int p = 0; p < TNP; p++) {
                part[0][p] = ffma2(a0, bq[p], part[0][p]);
                part[1][p] = ffma2(a1, bq[p], part[1][p]);
            }
        }
        #pragma unroll
        for (int t = 0; t < 2; t++)
            #pragma unroll
            for (int p = 0; p < TNP; p++) {
                u64 y = ffma2(cmp[t][p], neg1, part[t][p]);
                u64 s = add2(acc[t][p], y);
                u64 d = ffma2(acc[t][p], neg1, s);
                cmp[t][p] = ffma2(y, neg1, d);
                acc[t][p] = s;
            }
        __syncthreads();
    }

    float* Cb = Cpart + (size_t)kz * PSTRIDE;
    #pragma unroll
    for (int t = 0; t < 2; t++) {
        int grow = row0 + rowg + t * RP;
        if (grow < M) {
            #pragma unroll
            for (int p = 0; p < TNP; p++) {
                float lo, hi; unpack2(acc[t][p], lo, hi);
                Cb[(size_t)grow * NC + colg * TN + 2 * p]     = lo;
                Cb[(size_t)grow * NC + colg * TN + 2 * p + 1] = hi;
            }
        }
    }
}

// Y[m, 0..48) = act( sum_splits T[m, col0..col0+48) + b + add )
__global__ void ss_kernel(const float* __restrict__ T, int srcNC, int col0, int nsplit,
                          const float* __restrict__ b, int act,
                          const float* __restrict__ add, float* __restrict__ Y, int M)
{
    int e = blockIdx.x * blockDim.x + threadIdx.x;
    if (e >= M * 12) return;
    int m = e / 12, j4 = e - m * 12;
    size_t off = (size_t)m * srcNC + col0 + j4 * 4;
    float4 s = *reinterpret_cast<const float4*>(T + off);
    for (int sp = 1; sp < nsplit; sp++) {
        float4 v = *reinterpret_cast<const float4*>(T + (size_t)sp * PSTRIDE + off);
        s.x += v.x; s.y += v.y; s.z += v.z; s.w += v.w;
    }
    if (b) {
        float4 bb = *reinterpret_cast<const float4*>(b + j4 * 4);
        s.x += bb.x; s.y += bb.y; s.z += bb.z; s.w += bb.w;
    }
    if (add) {
        float4 av = *reinterpret_cast<const float4*>(add + (size_t)m * 48 + j4 * 4);
        s.x += av.x; s.y += av.y; s.z += av.z; s.w += av.w;
    }
    if (act == 1) {
        s.x = fmaxf(s.x, 0.f); s.y = fmaxf(s.y, 0.f);
        s.z = fmaxf(s.z, 0.f); s.w = fmaxf(s.w, 0.f);
    }
    *reinterpret_cast<float4*>(Y + (size_t)m * 48 + j4 * 4) = s;
}

// small GEMM: out[m, ocol..ocol+48) = act( f(X[m,:ncin]) @ W[48,ncin]^T + b + b2 )
__global__ __launch_bounds__(256)
void sgemm_kernel(const float* __restrict__ X, int M, int ncin,
                  const float* __restrict__ W, const float* __restrict__ b,
                  const float* __restrict__ b2, const float* __restrict__ alpha_p,
                  int act, int insig, float* __restrict__ out, int ostride, int ocol)
{
    __shared__ float Xs[32][129];
    __shared__ float Wt[128][50];
    const int tid = threadIdx.x;
    const int row0 = blockIdx.x * 32;
    for (int idx = tid; idx < (48 * ncin) / 2; idx += 256) {
        int e = idx * 2;
        int j = e / ncin, i = e - j * ncin;
        float2 w = *reinterpret_cast<const float2*>(W + e);
        Wt[i][j] = w.x; Wt[i + 1][j] = w.y;
    }
    for (int idx = tid; idx < 32 * ncin; idx += 256) {
        int r = idx / ncin, c = idx - r * ncin;
        int g = row0 + r;
        float v = (g < M) ? X[(size_t)g * ncin + c] : 0.f;
        if (insig) v = 1.f / (1.f + expf(-v));
        Xs[r][c] = v;
    }
    __syncthreads();
    const int m = tid & 31, jg = tid >> 5;
    u64 acc[3] = {0ull, 0ull, 0ull};
    #pragma unroll 8
    for (int i = 0; i < ncin; i++) {
        float a = Xs[m][i];
        u64 av = pack2(a, a);
        const u64* wp = reinterpret_cast<const u64*>(&Wt[i][jg * 6]);
        acc[0] = ffma2(av, wp[0], acc[0]);
        acc[1] = ffma2(av, wp[1], acc[1]);
        acc[2] = ffma2(av, wp[2], acc[2]);
    }
    int g = row0 + m;
    if (g < M) {
        float al = alpha_p ? *alpha_p : 0.f;
        #pragma unroll
        for (int p = 0; p < 3; p++) {
            float lo, hi; unpack2(acc[p], lo, hi);
            int j = jg * 6 + 2 * p;
            if (b)  { lo += b[j];  hi += b[j + 1]; }
            if (b2) { lo += b2[j]; hi += b2[j + 1]; }
            if (act == 2) { if (lo < 0.f) lo *= al; if (hi < 0.f) hi *= al; }
            out[(size_t)g * ostride + ocol + j]     = lo;
            out[(size_t)g * ostride + ocol + j + 1] = hi;
        }
    }
}

__global__ void sc_kernel(const float* __restrict__ h1, const float* __restrict__ P,
                          const int* __restrict__ perm, const float* __restrict__ db_p,
                          float* __restrict__ ret, unsigned long long* __restrict__ keys, int M)
{
    int n = blockIdx.x * blockDim.x + threadIdx.x;
    if (n >= NN) return;
    if (n < M) {
        float db = *db_p;
        const float* pr = P + (size_t)n * 48;
        const float* h  = h1 + (size_t)n * 48;
        const float* h2 = h1 + (size_t)perm[n] * 48;
        double s1 = 0.0, s2 = 0.0;
        #pragma unroll 8
        for (int i = 0; i < 48; i++) {
            s1 = fma((double)h[i],  (double)pr[i], s1);
            s2 = fma((double)h2[i], (double)pr[i], s2);
        }
        float s1f = (float)s1 + db, s2f = (float)s2 + db;
        ret[n] = s1f; ret[M + n] = s2f;
        float score = 1.f / (1.f + expf(-s1f));
        keys[n] = ((unsigned long long)(~__float_as_uint(score)) << 32) | (unsigned)n;
    } else {
        keys[n] = (0xFFFFFFFFull << 32) | (unsigned)n;
    }
}

__global__ void sort_kernel(const unsigned long long* __restrict__ keys,
                            int* __restrict__ idx_out, float* __restrict__ val_out, int topk)
{
    extern __shared__ unsigned long long s[];
    const int n = NN;
    for (int i = threadIdx.x; i < n; i += blockDim.x) s[i] = keys[i];
    __syncthreads();
    for (int k = 2; k <= n; k <<= 1)
        for (int j = k >> 1; j > 0; j >>= 1) {
            for (int t = threadIdx.x; t < n; t += blockDim.x) {
                int ixj = t ^ j;
                if (ixj > t) {
                    bool up = ((t & k) == 0);
                    unsigned long long xv = s[t], yv = s[ixj];
                    if ((xv > yv) == up) { s[t] = yv; s[ixj] = xv; }
                }
            }
            __syncthreads();
        }
    for (int r = threadIdx.x; r < topk; r += blockDim.x) {
        unsigned long long kv = s[r];
        idx_out[r] = (int)(kv & 0xffffffffu);
        val_out[r] = __uint_as_float(~(unsigned int)(kv >> 32));
    }
}

__global__ void poolgather_kernel(const float* __restrict__ X, const int* __restrict__ idx,
                                  const float* __restrict__ val, float* __restrict__ Y, int Kn)
{
    int e = blockIdx.x * blockDim.x + threadIdx.x;
    if (e >= Kn * 48) return;
    int r = e / 48, c = e - r * 48;
    Y[e] = X[(size_t)idx[r] * 48 + c] * val[r];
}

__global__ void scatter2_kernel(const float* __restrict__ X, const int* __restrict__ idx,
                                int Kn, float* __restrict__ Z, int zstride, int col0)
{
    int e = blockIdx.x * blockDim.x + threadIdx.x;
    if (e >= Kn * 48) return;
    int r = e / 48, c = e - r * 48;
    Z[(size_t)idx[r] * zstride + col0 + c] = X[e];
}

__global__ void combine_kernel(const float* __restrict__ a, const float* __restrict__ b, float sb,
                               const float* __restrict__ c, float sc,
                               const float* __restrict__ d, float* __restrict__ o, int n)
{
    int i = blockIdx.x * blockDim.x + threadIdx.x;
    if (i >= n) return;
    float v = fmaf(sb, b[i], a[i]);
    if (c) v = fmaf(sc, c[i], v);
    if (d) v += d[i];
    o[i] = v;
}

__global__ void cat_kernel(const float* __restrict__ xa, const float* __restrict__ xo,
                           float* __restrict__ cat, int M)
{
    int e = blockIdx.x * blockDim.x + threadIdx.x;
    if (e >= M * 96) return;
    int m = e / 96, c = e - m * 96;
    cat[e] = (c < 48) ? xa[(size_t)m * 48 + c] : xo[(size_t)m * 48 + (c - 48)];
}

// out[i][j] = A[idx[i]][idx[j]]: stage full source row in smem (coalesced LDG),
// then gather from smem. Kills the 8x sector amplification of random global reads.
__global__ void gatherA_kernel(const float* __restrict__ A, int lda,
                               const int* __restrict__ idx, int Ksz, float* __restrict__ out)
{
    extern __shared__ float srow[];
    const float* arow = A + (size_t)__ldg(&idx[blockIdx.x]) * lda;
    int lda4 = lda >> 2;
    for (int j = threadIdx.x; j < lda4; j += blockDim.x)
        reinterpret_cast<float4*>(srow)[j] = reinterpret_cast<const float4*>(arow)[j];
    __syncthreads();
    float* orow = out + (size_t)blockIdx.x * Ksz;
    for (int j = threadIdx.x; j < Ksz; j += blockDim.x)
        orow[j] = srow[__ldg(&idx[j])];
}

static void* symaddr(const void* sym) { void* p = nullptr; cudaGetSymbolAddress(&p, sym); return p; }

extern "C" void kernel_launch(void* const* d_in, const int* in_sizes, int n_in,
                              void* d_out, int out_size)
{
    const float* A      = (const float*)d_in[0];
    const float* x      = (const float*)d_in[1];
    const int*   perm1  = (const int*)  d_in[2];
    const int*   perm2  = (const int*)  d_in[3];
    const float* W_in   = (const float*)d_in[4];
    const float* b_in   = (const float*)d_in[5];
    const float* W_dd   = (const float*)d_in[6];
    const float* b_dd   = (const float*)d_in[7];
    const float* W_end  = (const float*)d_in[8];
    const float* b_end  = (const float*)d_in[9];
    const float* mlp_b2 = (const float*)d_in[10];
    const float* prelu_a= (const float*)d_in[11];
    const float* disc_W = (const float*)d_in[12];
    const float* disc_b = (const float*)d_in[13];

    float* out  = (float*)d_out;
    float* ret1 = out + (size_t)NN * 48;
    float* ret2 = ret1 + 2 * NN;

    float* A2  = (float*)symaddr(g_A2);   float* A3  = (float*)symaddr(g_A3);
    float* T   = (float*)symaddr(g_T);
    float* xs1 = (float*)symaddr(g_xs1);  float* xs2 = (float*)symaddr(g_xs2);
    float* xs3 = (float*)symaddr(g_xs3);  float* xorg= (float*)symaddr(g_xorg);
    float* u1  = (float*)symaddr(g_u1);   float* u2  = (float*)symaddr(g_u2);
    float* u3  = (float*)symaddr(g_u3);
    float* xd1 = (float*)symaddr(g_xd1);  float* xd2 = (float*)symaddr(g_xd2);
    float* h1  = (float*)symaddr(g_h1);   float* P   = (float*)symaddr(g_P);
    float* pre = (float*)symaddr(g_pre);
    float* y1  = (float*)symaddr(g_y1);   float* y2  = (float*)symaddr(g_y2);
    float* y3  = (float*)symaddr(g_y3);
    float* x12 = (float*)symaddr(g_x12);  float* x21 = (float*)symaddr(g_x21);
    float* x23 = (float*)symaddr(g_x23);  float* x32 = (float*)symaddr(g_x32);
    float* Z   = (float*)symaddr(g_Z);    float* tmp = (float*)symaddr(g_tmp);
    float* tmp2= (float*)symaddr(g_tmp2); float* B96 = (float*)symaddr(g_cat);
    float* val1= (float*)symaddr(g_val1); float* val2= (float*)symaddr(g_val2);
    int* idx1  = (int*)symaddr(g_idx1);   int* idx2  = (int*)symaddr(g_idx2);
    unsigned long long* keys = (unsigned long long*)symaddr(g_keys);

    cudaFuncSetAttribute(sort_kernel, cudaFuncAttributeMaxDynamicSharedMemorySize, NN * 8);
    cudaFuncSetAttribute(gatherA_kernel, cudaFuncAttributeMaxDynamicSharedMemorySize, NN * 4);

    const int NSPL = 8;
    #define Wd(i) (W_dd + (size_t)(i) * 2304)
    #define bd(i) (b_dd + (i) * 48)

    auto sg = [&](const float* X, int M, int ncin, const float* W, const float* b,
                  const float* b2, const float* ap, int act, int insig,
                  float* o, int ostride, int ocol) {
        sgemm_kernel<<<(M + 31) / 32, 256>>>(X, M, ncin, W, b, b2, ap, act, insig, o, ostride, ocol);
    };
    auto g48 = [&](const float* Am, int lda, const float* Bm, int M, int K) {
        dim3 g((M + 127) / 128, NSPL);
        gemm3_kernel<48, 12><<<g, 256>>>(Am, lda, Bm, T, M, K, NSPL);
    };
    auto g96 = [&](const float* Am, int lda, const float* Bm, int M, int K) {
        dim3 g((M + 63) / 64, NSPL);
        gemm3_kernel<96, 12><<<g, 256>>>(Am, lda, Bm, T, M, K, NSPL);
    };
    auto ss = [&](int srcNC, int col0, const float* b, int act, const float* add,
                  float* Y, int M) {
        ss_kernel<<<(M * 12 + 255) / 256, 256>>>(T, srcNC, col0, NSPL, b, act, add, Y, M);
    };
    auto pg = [&](const float* X, const int* idx, const float* val, float* Y, int Kn) {
        poolgather_kernel<<<(Kn * 48 + 255) / 256, 256>>>(X, idx, val, Y, Kn);
    };
    auto sct = [&](const float* X, const int* idx, int Kn, float* Zb, int zstride, int col0) {
        scatter2_kernel<<<(Kn * 48 + 255) / 256, 256>>>(X, idx, Kn, Zb, zstride, col0);
    };
    auto comb = [&](const float* a, const float* b, float sb, const float* c, float sc,
                    const float* d, float* o, int n) {
        combine_kernel<<<(n + 255) / 256, 256>>>(a, b, sb, c, sc, d, o, n);
    };
    auto gcn = [&](const float* Am, int lda, int Mk, const float* X, const float* W,
                   const float* b, int act, const float* add, float* Y) {
        sg(X, Mk, 48, W, nullptr, nullptr, nullptr, 0, 0, pre, 48, 0);
        g48(Am, lda, pre, Mk, Mk);
        ss(48, 0, b, act, add, Y, Mk);
    };
    auto cross_pair = [&](const float* Am, int lda, int Mk,
                          const float* Xa, const float* Wa, const float* ba, float* Ya,
                          const float* Xb, int Mb, const float* Wb, const float* bb, float* Yb,
                          const int* idx) {
        cudaMemsetAsync(B96, 0, (size_t)Mk * 96 * sizeof(float));
        sg(Xa, Mk, 48, Wa, nullptr, nullptr, nullptr, 0, 0, B96, 96, 0);
        sg(Xb, Mb, 48, Wb, nullptr, nullptr, nullptr, 0, 0, pre, 48, 0);
        sct(pre, idx, Mb, B96, 96, 48);
        g96(Am, lda, B96, Mk, Mk);
        ss(96, 0,  ba, 0, nullptr, Ya, Mk);
        ss(96, 48, bb, 0, nullptr, Yb, Mk);
    };

    // ---- phase 0: x_s1 = A @ (x @ W_in^T) + b_in ----
    sg(x, NN, 128, W_in, nullptr, nullptr, nullptr, 0, 0, pre, 48, 0);
    g48(A, NN, pre, NN, NN);
    ss(48, 0, b_in, 0, nullptr, xs1, NN);
    cudaMemcpyAsync(xorg, xs1, (size_t)NN * 48 * sizeof(float), cudaMemcpyDeviceToDevice);

    // ---- index_select scale 1 (fc=1, gcn=2, m=0) ----
    sg(xs1, NN, 48, Wd(1), bd(1), mlp_b2, prelu_a, 2, 0, h1, 48, 0);
    gcn(A, NN, NN, h1, Wd(2), bd(2), 0, nullptr, xd1);
    sg(xd1, NN, 48, disc_W, nullptr, nullptr, nullptr, 0, 1, P, 48, 0);
    sc_kernel<<<NN / 256, 256>>>(h1, P, perm1, disc_b + 0, ret1, keys, NN);
    sort_kernel<<<1, 1024, NN * 8>>>(keys, idx1, val1, KK1);
    pg(xs1, idx1, val1, xs2, KK1);
    gatherA_kernel<<<KK1, 256, NN * 4>>>(A, NN, idx1, KK1, A2);
    gcn(A2, KK1, KK1, xs2, Wd(0), bd(0), 0, nullptr, xs2);

    // ---- index_select scale 2 (fc=3, gcn=4, m=1) ----
    sg(xs2, KK1, 48, Wd(3), bd(3), mlp_b2 + 48, prelu_a + 1, 2, 0, h1, 48, 0);
    gcn(A2, KK1, KK1, h1, Wd(4), bd(4), 0, nullptr, xd2);
    sg(xd2, KK1, 48, disc_W + 2304, nullptr, nullptr, nullptr, 0, 1, P, 48, 0);
    sc_kernel<<<NN / 256, 256>>>(h1, P, perm2, disc_b + 1, ret2, keys, KK1);
    sort_kernel<<<1, 1024, NN * 8>>>(keys, idx2, val2, KK2);
    pg(xs2, idx2, val2, xs3, KK2);
    gatherA_kernel<<<KK2, 256, KK1 * 4>>>(A2, KK1, idx2, KK2, A3);

    // ---- layer 1 ----
    gcn(A,  NN,  NN,  xs1, Wd(5),  bd(5),  1, nullptr, y1);
    gcn(A2, KK1, KK1, xs2, Wd(8),  bd(8),  1, nullptr, y2);
    gcn(A3, KK2, KK2, xs3, Wd(11), bd(11), 1, nullptr, y3);
    cross_pair(A, NN, NN,  y1, Wd(14), bd(14), tmp,  y2, KK1, Wd(15), bd(15), x21, idx1);
    pg(tmp, idx1, val1, x12, KK1);
    cross_pair(A2, KK1, KK1, y2, Wd(16), bd(16), tmp, y3, KK2, Wd(17), bd(17), x32, idx2);
    pg(tmp, idx2, val2, x23, KK2);
    comb(y1, x21, 1.f,  nullptr, 0.f, xs1, u1, NN * 48);
    comb(y2, x12, 0.5f, x32, 0.5f,    xs2, u2, KK1 * 48);
    comb(y3, x23, 1.f,  nullptr, 0.f, xs3, u3, KK2 * 48);

    // ---- layer 2 ----
    gcn(A,  NN,  NN,  u1, Wd(6),  bd(6),  1, nullptr, y1);
    gcn(A2, KK1, KK1, u2, Wd(9),  bd(9),  1, nullptr, y2);
    gcn(A3, KK2, KK2, u3, Wd(12), bd(12), 1, nullptr, y3);
    cross_pair(A, NN, NN,  y1, Wd(18), bd(18), tmp,  y2, KK1, Wd(19), bd(19), x21, idx1);
    pg(tmp, idx1, val1, x12, KK1);
    cross_pair(A2, KK1, KK1, y2, Wd(20), bd(20), tmp, y3, KK2, Wd(21), bd(21), x32, idx2);
    pg(tmp, idx2, val2, x23, KK2);
    comb(y1, x21, 0.05f,  nullptr, 0.f, nullptr, xs1, NN * 48);
    comb(y2, x12, 0.025f, x32, 0.025f,  nullptr, xs2, KK1 * 48);
    comb(y3, x23, 0.05f,  nullptr, 0.f, nullptr, xs3, KK2 * 48);

    // ---- layer 3 ----
    gcn(A,  NN,  NN,  xs1, Wd(7),  bd(7),  1, nullptr, y1);
    gcn(A2, KK1, KK1, xs2, Wd(10), bd(10), 1, nullptr, y2);
    gcn(A3, KK2, KK2, xs3, Wd(13), bd(13), 1, nullptr, y3);

    // ---- fuse ----
    sg(y3, KK2, 48, Wd(23), nullptr, nullptr, nullptr, 0, 0, pre, 48, 0);
    cudaMemsetAsync(Z, 0, (size_t)KK1 * 48 * sizeof(float));
    sct(pre, idx2, KK2, Z, 48, 0);
    g48(A2, KK1, Z, KK1, KK1);
    ss(48, 0, bd(23), 0, xd2, tmp, KK1);
    comb(y2, tmp, 1.f, nullptr, 0.f, nullptr, tmp2, KK1 * 48);
    sg(tmp2, KK1, 48, Wd(22), nullptr, nullptr, nullptr, 0, 0, pre, 48, 0);
    cudaMemsetAsync(Z, 0, (size_t)NN * 48 * sizeof(float));
    sct(pre, idx1, KK1, Z, 48, 0);
    g48(A, NN, Z, NN, NN);
    ss(48, 0, bd(22), 0, nullptr, tmp, NN);
    comb(y1, tmp, 1.f, xd1, 1.f, nullptr, tmp2, NN * 48);
    cat_kernel<<<(NN * 96 + 255) / 256, 256>>>(tmp2, xorg, B96, NN);
    sg(B96, NN, 96, W_end, nullptr, nullptr, nullptr, 0, 0, pre, 48, 0);
    g48(A, NN, pre, NN, NN);
    ss(48, 0, b_end, 0, nullptr, out, NN);
}